// round 13
// baseline (speedup 1.0000x reference)
#include <cuda_runtime.h>
#include <cuda_bf16.h>
#include <cstdint>
#include <cstddef>

// ============================================================================
// Problem dims
// ============================================================================
#define MM 8192
#define KK 4096
#define NN 4096

// ============================================================================
// Device scratch (allowed: __device__ globals, no runtime allocation)
// ============================================================================
__device__ unsigned g_amax_x;
__device__ unsigned g_amax_w;
__device__ __nv_bfloat16 g_xq[(size_t)MM * KK];   // quantized activations (exact ints in bf16)
__device__ __nv_bfloat16 g_wq[(size_t)NN * KK];   // quantized weights

// ============================================================================
// PTX helpers — family-generic (sm_80+ PTX only; NO tcgen05 on this target!)
// ============================================================================
__device__ __forceinline__ uint32_t smem_u32(const void* p) {
    uint32_t a;
    asm("{ .reg .u64 t; cvta.to.shared.u64 t, %1; cvt.u32.u64 %0, t; }" : "=r"(a) : "l"(p));
    return a;
}

#define CP_ASYNC16(dst, src) \
    asm volatile("cp.async.cg.shared.global [%0], [%1], 16;" :: "r"(dst), "l"(src) : "memory")
#define CP_COMMIT() asm volatile("cp.async.commit_group;" ::: "memory")
#define CP_WAIT2()  asm volatile("cp.async.wait_group 2;" ::: "memory")
#define CP_WAIT0()  asm volatile("cp.async.wait_group 0;" ::: "memory")

// bf16 warp MMA: D(16x8,f32) = A(16x16,bf16,row) * B(16x8,bf16,col) + D
__device__ __forceinline__ void hmma16816(float* c, const uint32_t* a, const uint32_t* b) {
    asm volatile(
        "mma.sync.aligned.m16n8k16.row.col.f32.bf16.bf16.f32 "
        "{%0,%1,%2,%3}, {%4,%5,%6,%7}, {%8,%9}, {%0,%1,%2,%3};"
        : "+f"(c[0]), "+f"(c[1]), "+f"(c[2]), "+f"(c[3])
        : "r"(a[0]), "r"(a[1]), "r"(a[2]), "r"(a[3]), "r"(b[0]), "r"(b[1]));
}

// ldmatrix x4: four 8x8 b16 matrices; lane l supplies the row address for its group
__device__ __forceinline__ void ldsm_x4(uint32_t* r, uint32_t addr) {
    asm volatile("ldmatrix.sync.aligned.m8n8.x4.shared.b16 {%0,%1,%2,%3}, [%4];"
                 : "=r"(r[0]), "=r"(r[1]), "=r"(r[2]), "=r"(r[3]) : "r"(addr));
}

// ============================================================================
// Pass 0: reset scales
// ============================================================================
__global__ void reset_kernel() {
    g_amax_x = 0u;
    g_amax_w = 0u;
}

// ============================================================================
// Pass 1: fused abs-max over BOTH tensors in one launch
//   blocks [0, 2048) -> x ; blocks [2048, 3072) -> w
// ============================================================================
__global__ void absmax_both_kernel(const float* __restrict__ x, const float* __restrict__ w) {
    const bool is_w = blockIdx.x >= 2048;
    const float4* in4 = reinterpret_cast<const float4*>(is_w ? w : x);
    const long n4 = is_w ? ((long)NN * KK / 4) : ((long)MM * KK / 4);
    const long nb = is_w ? 1024 : 2048;
    const long bid = is_w ? (blockIdx.x - 2048) : blockIdx.x;

    float m = 0.0f;
    long i = bid * blockDim.x + threadIdx.x;
    const long stride = nb * blockDim.x;
    for (; i < n4; i += stride) {
        float4 v = in4[i];
        m = fmaxf(m, fmaxf(fmaxf(fabsf(v.x), fabsf(v.y)), fmaxf(fabsf(v.z), fabsf(v.w))));
    }
    #pragma unroll
    for (int o = 16; o > 0; o >>= 1)
        m = fmaxf(m, __shfl_xor_sync(0xFFFFFFFFu, m, o));
    if ((threadIdx.x & 31) == 0)
        atomicMax(is_w ? &g_amax_w : &g_amax_x, __float_as_uint(m));
}

// ============================================================================
// Pass 2: fused quantize of BOTH tensors — clip(rint(t/scale), ±127)
//   Values are integers in [-127,127]: exactly representable in bf16.
//   blocks [0, 8192) -> x ; blocks [8192, 12288) -> w
// ============================================================================
__global__ void quant_both_kernel(const float* __restrict__ x, const float* __restrict__ w) {
    const bool is_w = blockIdx.x >= 8192;
    const float4* in4 = reinterpret_cast<const float4*>(is_w ? w : x);
    __nv_bfloat162* q2 = reinterpret_cast<__nv_bfloat162*>(is_w ? g_wq : g_xq);
    const long n4 = is_w ? ((long)NN * KK / 4) : ((long)MM * KK / 4);
    const long nb = is_w ? 4096 : 8192;
    const long bid = is_w ? (blockIdx.x - 8192) : blockIdx.x;
    const float amax = __uint_as_float(is_w ? g_amax_w : g_amax_x);
    const float scale = amax / 127.0f;

    long i = bid * blockDim.x + threadIdx.x;
    const long stride = nb * blockDim.x;
    for (; i < n4; i += stride) {
        float4 v = in4[i];
        float a = fminf(fmaxf(rintf(v.x / scale), -127.0f), 127.0f);
        float b = fminf(fmaxf(rintf(v.y / scale), -127.0f), 127.0f);
        float c = fminf(fmaxf(rintf(v.z / scale), -127.0f), 127.0f);
        float d = fminf(fmaxf(rintf(v.w / scale), -127.0f), 127.0f);
        q2[2 * i + 0] = __floats2bfloat162_rn(a, b);
        q2[2 * i + 1] = __floats2bfloat162_rn(c, d);
    }
}

// ============================================================================
// Pass 3: bf16 GEMM  out[M,N] = Xq[M,K] @ Wq[N,K]^T * s + bias
//   BM=128, BN=128, BK=64 (128B rows, 144B padded); 256 threads = 8 warps in
//   4(M) x 2(N), warp tile 32x64; ldmatrix.x4; 4-stage cp.async; one barrier
//   per k-tile; OCCUPANCY 1 (255-reg budget).
//   NEW: register double-buffered fragments — while HMMAs of sub-step kpi
//   execute, the ldsm for kpi+1 are already in flight into the other buffer.
//   This breaks the per-kpi ldsm->HMMA dependency ramp *within* each warp,
//   which rounds 8-12 showed cannot be hidden by adding more barrier-aligned
//   warps (tensor pipe stuck at ~53% across all warp-count configs).
// ============================================================================
static constexpr int BK = 64;                  // bf16 elems per K chunk (128B rows)
static constexpr int NKT = KK / BK;            // 64 k-tiles
static constexpr int ROW_PAD = 144;            // 128B data + 16B pad (conflict-free)
static constexpr int A_STAGE = 128 * ROW_PAD;  // 18432 B
static constexpr int STAGE_BYTES = 2 * A_STAGE;// A + B = 36864 B
static constexpr int NSTAGE = 4;
static constexpr int SMEM_BYTES = NSTAGE * STAGE_BYTES;  // 147456 B (occ 1)

__device__ __forceinline__ void stage_copy(uint32_t sbase, int kt, int m0, int n0, int tid) {
    const size_t kofs = (size_t)kt * BK;       // element offset
    // A: 128 rows x 8 chunks of 16B = 1024 copies; 4 per thread
    #pragma unroll
    for (int i = 0; i < 4; i++) {
        int idx = tid + i * 256;               // 0..1023
        int row = idx >> 3, ch = idx & 7;
        CP_ASYNC16(sbase + row * ROW_PAD + ch * 16,
                   (const void*)(g_xq + (size_t)(m0 + row) * KK + kofs + ch * 8));
    }
    // B: 128 rows x 8 chunks
    #pragma unroll
    for (int i = 0; i < 4; i++) {
        int idx = tid + i * 256;
        int row = idx >> 3, ch = idx & 7;
        CP_ASYNC16(sbase + A_STAGE + row * ROW_PAD + ch * 16,
                   (const void*)(g_wq + (size_t)(n0 + row) * KK + kofs + ch * 8));
    }
}

// Load one kpi's fragments (A: 2 ldsm.x4, B: 4 ldsm.x4) into a register buffer.
__device__ __forceinline__ void load_frags(uint32_t sA, uint32_t sB, int kp,
                                           int warp_m, int warp_n, int lrow, int lhalf,
                                           uint32_t a[2][4], uint32_t b[8][2]) {
    #pragma unroll
    for (int mt = 0; mt < 2; mt++)
        ldsm_x4(a[mt], sA + (warp_m * 32 + mt * 16 + lrow) * ROW_PAD + kp * 32 + lhalf);
    #pragma unroll
    for (int np = 0; np < 4; np++) {
        uint32_t r[4];
        ldsm_x4(r, sB + (warp_n * 64 + np * 16 + lrow) * ROW_PAD + kp * 32 + lhalf);
        b[2 * np + 0][0] = r[0]; b[2 * np + 0][1] = r[2];
        b[2 * np + 1][0] = r[1]; b[2 * np + 1][1] = r[3];
    }
}

extern "C" __global__ void __launch_bounds__(256, 1)
gemm_kernel(const float* __restrict__ bias, float* __restrict__ out) {
    extern __shared__ char smem[];
    const uint32_t sb = smem_u32(smem);
    const int tid = threadIdx.x;
    const int wid = tid >> 5;
    const int lane = tid & 31;
    const int warp_m = wid & 3;          // 4 warps along M (32 rows each)
    const int warp_n = wid >> 2;         // 2 warps along N (64 cols each)
    const int m0 = blockIdx.y * 128;
    const int n0 = blockIdx.x * 128;

    float c[2][8][4];
    #pragma unroll
    for (int mt = 0; mt < 2; mt++)
        #pragma unroll
        for (int nt = 0; nt < 8; nt++)
            #pragma unroll
            for (int j = 0; j < 4; j++) c[mt][nt][j] = 0.0f;

    // Prologue: fill stages 0..2
    #pragma unroll
    for (int s = 0; s < NSTAGE - 1; s++) {
        stage_copy(sb + s * STAGE_BYTES, s, m0, n0, tid);
        CP_COMMIT();
    }

    // ldmatrix lane addressing: row = lane&15, +16B for lanes 16..31
    const int lrow = lane & 15;
    const int lhalf = (lane >> 4) * 16;

    // Double-buffered fragment registers
    uint32_t afr[2][2][4], bfr[2][8][2];

    for (int kt = 0; kt < NKT; kt++) {
        CP_WAIT2();            // stage kt resident (3 groups pending -> wait to 2)
        __syncthreads();       // visibility + write-safety for the copy below

        // Copy stage kt+3 into buffer (kt+3)%4 == (kt-1)%4 (compute done at kt-1).
        if (kt + NSTAGE - 1 < NKT)
            stage_copy(sb + ((kt + NSTAGE - 1) % NSTAGE) * STAGE_BYTES,
                       kt + NSTAGE - 1, m0, n0, tid);
        CP_COMMIT();

        const uint32_t sA = sb + (kt % NSTAGE) * STAGE_BYTES;
        const uint32_t sB = sA + A_STAGE;

        // Software-pipelined kpi loop: load kpi+1 while computing kpi.
        load_frags(sA, sB, 0, warp_m, warp_n, lrow, lhalf, afr[0], bfr[0]);
        #pragma unroll
        for (int kpi = 0; kpi < 4; kpi++) {
            const int cur = kpi & 1, nxt = cur ^ 1;
            if (kpi < 3)
                load_frags(sA, sB, kpi + 1, warp_m, warp_n, lrow, lhalf, afr[nxt], bfr[nxt]);
            #pragma unroll
            for (int mt = 0; mt < 2; mt++)
                #pragma unroll
                for (int nt = 0; nt < 8; nt++)
                    hmma16816(c[mt][nt], afr[cur][mt], bfr[cur][nt]);
        }
    }
    CP_WAIT0();

    // Epilogue: dequant + bias
    const float sx = __uint_as_float(g_amax_x) / 127.0f;
    const float sw = __uint_as_float(g_amax_w) / 127.0f;
    const float s = sx * sw;

    #pragma unroll
    for (int mt = 0; mt < 2; mt++) {
        #pragma unroll
        for (int half = 0; half < 2; half++) {
            int row = m0 + warp_m * 32 + mt * 16 + (lane >> 2) + half * 8;
            float* orow = out + (size_t)row * NN;
            #pragma unroll
            for (int nt = 0; nt < 8; nt++) {
                int col = n0 + warp_n * 64 + nt * 8 + (lane & 3) * 2;
                float2 o;
                o.x = c[mt][nt][half * 2 + 0] * s + __ldg(&bias[col]);
                o.y = c[mt][nt][half * 2 + 1] * s + __ldg(&bias[col + 1]);
                *reinterpret_cast<float2*>(orow + col) = o;
            }
        }
    }
}

// ============================================================================
// kernel_launch — graph-capturable, allocation-free
// ============================================================================
extern "C" void kernel_launch(void* const* d_in, const int* in_sizes, int n_in,
                              void* d_out, int out_size) {
    const float* x    = (const float*)d_in[0];   // [M, K]
    const float* w    = (const float*)d_in[1];   // [N, K]
    const float* bias = (const float*)d_in[2];   // [N]
    float* out        = (float*)d_out;           // [M, N]

    reset_kernel<<<1, 1>>>();
    absmax_both_kernel<<<3072, 256>>>(x, w);
    quant_both_kernel<<<12288, 256>>>(x, w);

    static bool attr_set = false;
    if (!attr_set) {
        cudaFuncSetAttribute(gemm_kernel, cudaFuncAttributeMaxDynamicSharedMemorySize, SMEM_BYTES);
        attr_set = true;
    }
    gemm_kernel<<<dim3(NN / 128, MM / 128, 1), 256, SMEM_BYTES>>>(bias, out);
}

// round 14
// speedup vs baseline: 1.0993x; 1.0993x over previous
#include <cuda_runtime.h>
#include <cuda_bf16.h>
#include <cstdint>
#include <cstddef>

// ============================================================================
// Problem dims
// ============================================================================
#define MM 8192
#define KK 4096
#define NN 4096

// ============================================================================
// Device scratch (allowed: __device__ globals, no runtime allocation)
// ============================================================================
__device__ unsigned g_amax_x;
__device__ unsigned g_amax_w;
__device__ __nv_bfloat16 g_xq[(size_t)MM * KK];   // quantized activations (exact ints in bf16)
__device__ __nv_bfloat16 g_wq[(size_t)NN * KK];   // quantized weights

// ============================================================================
// PTX helpers — family-generic (sm_80+ PTX only; NO tcgen05 on this target!)
// ============================================================================
__device__ __forceinline__ uint32_t smem_u32(const void* p) {
    uint32_t a;
    asm("{ .reg .u64 t; cvta.to.shared.u64 t, %1; cvt.u32.u64 %0, t; }" : "=r"(a) : "l"(p));
    return a;
}

#define CP_ASYNC16(dst, src) \
    asm volatile("cp.async.cg.shared.global [%0], [%1], 16;" :: "r"(dst), "l"(src) : "memory")
#define CP_COMMIT() asm volatile("cp.async.commit_group;" ::: "memory")
#define CP_WAIT1()  asm volatile("cp.async.wait_group 1;" ::: "memory")
#define CP_WAIT0()  asm volatile("cp.async.wait_group 0;" ::: "memory")

// bf16 warp MMA: D(16x8,f32) = A(16x16,bf16,row) * B(16x8,bf16,col) + D
__device__ __forceinline__ void hmma16816(float* c, const uint32_t* a, const uint32_t* b) {
    asm volatile(
        "mma.sync.aligned.m16n8k16.row.col.f32.bf16.bf16.f32 "
        "{%0,%1,%2,%3}, {%4,%5,%6,%7}, {%8,%9}, {%0,%1,%2,%3};"
        : "+f"(c[0]), "+f"(c[1]), "+f"(c[2]), "+f"(c[3])
        : "r"(a[0]), "r"(a[1]), "r"(a[2]), "r"(a[3]), "r"(b[0]), "r"(b[1]));
}

// ldmatrix x4: four 8x8 b16 matrices; lane l supplies the row address for its group
__device__ __forceinline__ void ldsm_x4(uint32_t* r, uint32_t addr) {
    asm volatile("ldmatrix.sync.aligned.m8n8.x4.shared.b16 {%0,%1,%2,%3}, [%4];"
                 : "=r"(r[0]), "=r"(r[1]), "=r"(r[2]), "=r"(r[3]) : "r"(addr));
}

// ============================================================================
// Pass 0: reset scales
// ============================================================================
__global__ void reset_kernel() {
    g_amax_x = 0u;
    g_amax_w = 0u;
}

// ============================================================================
// Pass 1: fused abs-max over BOTH tensors in one launch
//   blocks [0, 2048) -> x ; blocks [2048, 3072) -> w
// ============================================================================
__global__ void absmax_both_kernel(const float* __restrict__ x, const float* __restrict__ w) {
    const bool is_w = blockIdx.x >= 2048;
    const float4* in4 = reinterpret_cast<const float4*>(is_w ? w : x);
    const long n4 = is_w ? ((long)NN * KK / 4) : ((long)MM * KK / 4);
    const long nb = is_w ? 1024 : 2048;
    const long bid = is_w ? (blockIdx.x - 2048) : blockIdx.x;

    float m = 0.0f;
    long i = bid * blockDim.x + threadIdx.x;
    const long stride = nb * blockDim.x;
    for (; i < n4; i += stride) {
        float4 v = in4[i];
        m = fmaxf(m, fmaxf(fmaxf(fabsf(v.x), fabsf(v.y)), fmaxf(fabsf(v.z), fabsf(v.w))));
    }
    #pragma unroll
    for (int o = 16; o > 0; o >>= 1)
        m = fmaxf(m, __shfl_xor_sync(0xFFFFFFFFu, m, o));
    if ((threadIdx.x & 31) == 0)
        atomicMax(is_w ? &g_amax_w : &g_amax_x, __float_as_uint(m));
}

// ============================================================================
// Pass 2: fused quantize of BOTH tensors — clip(rint(t/scale), ±127)
//   Values are integers in [-127,127]: exactly representable in bf16.
//   blocks [0, 8192) -> x ; blocks [8192, 12288) -> w
// ============================================================================
__global__ void quant_both_kernel(const float* __restrict__ x, const float* __restrict__ w) {
    const bool is_w = blockIdx.x >= 8192;
    const float4* in4 = reinterpret_cast<const float4*>(is_w ? w : x);
    __nv_bfloat162* q2 = reinterpret_cast<__nv_bfloat162*>(is_w ? g_wq : g_xq);
    const long n4 = is_w ? ((long)NN * KK / 4) : ((long)MM * KK / 4);
    const long nb = is_w ? 4096 : 8192;
    const long bid = is_w ? (blockIdx.x - 8192) : blockIdx.x;
    const float amax = __uint_as_float(is_w ? g_amax_w : g_amax_x);
    const float scale = amax / 127.0f;

    long i = bid * blockDim.x + threadIdx.x;
    const long stride = nb * blockDim.x;
    for (; i < n4; i += stride) {
        float4 v = in4[i];
        float a = fminf(fmaxf(rintf(v.x / scale), -127.0f), 127.0f);
        float b = fminf(fmaxf(rintf(v.y / scale), -127.0f), 127.0f);
        float c = fminf(fmaxf(rintf(v.z / scale), -127.0f), 127.0f);
        float d = fminf(fmaxf(rintf(v.w / scale), -127.0f), 127.0f);
        q2[2 * i + 0] = __floats2bfloat162_rn(a, b);
        q2[2 * i + 1] = __floats2bfloat162_rn(c, d);
    }
}

// ============================================================================
// Pass 3: bf16 GEMM  out[M,N] = Xq[M,K] @ Wq[N,K]^T * s + bias
//   BM=128, BN=128, BK=64 (128B rows, 144B padded); 256 threads = 8 warps in
//   4(M) x 2(N), warp tile 32x64; ldmatrix.x4; 3-stage cp.async; one barrier
//   per k-tile.
//   Round-14 combination: register double-buffered fragments (round 13, which
//   compiled to 120 regs) + occupancy 2 (16 warps/SM, rounds 8-12). Both the
//   warp-level and ILP-level latency-hiding levers at once; every profile
//   showed neither pipe saturated (tensor ~50%, L1 ~43%, issue ~28%) =>
//   latency-bound, so in-flight work is the binding resource.
// ============================================================================
static constexpr int BK = 64;                  // bf16 elems per K chunk (128B rows)
static constexpr int NKT = KK / BK;            // 64 k-tiles
static constexpr int ROW_PAD = 144;            // 128B data + 16B pad (conflict-free)
static constexpr int A_STAGE = 128 * ROW_PAD;  // 18432 B
static constexpr int STAGE_BYTES = 2 * A_STAGE;// A + B = 36864 B
static constexpr int NSTAGE = 3;
static constexpr int SMEM_BYTES = NSTAGE * STAGE_BYTES;  // 110592 B (2 CTAs/SM)

__device__ __forceinline__ void stage_copy(uint32_t sbase, int kt, int m0, int n0, int tid) {
    const size_t kofs = (size_t)kt * BK;       // element offset
    // A: 128 rows x 8 chunks of 16B = 1024 copies; 4 per thread
    #pragma unroll
    for (int i = 0; i < 4; i++) {
        int idx = tid + i * 256;               // 0..1023
        int row = idx >> 3, ch = idx & 7;
        CP_ASYNC16(sbase + row * ROW_PAD + ch * 16,
                   (const void*)(g_xq + (size_t)(m0 + row) * KK + kofs + ch * 8));
    }
    // B: 128 rows x 8 chunks
    #pragma unroll
    for (int i = 0; i < 4; i++) {
        int idx = tid + i * 256;
        int row = idx >> 3, ch = idx & 7;
        CP_ASYNC16(sbase + A_STAGE + row * ROW_PAD + ch * 16,
                   (const void*)(g_wq + (size_t)(n0 + row) * KK + kofs + ch * 8));
    }
}

// Load one kpi's fragments (A: 2 ldsm.x4, B: 4 ldsm.x4) into a register buffer.
__device__ __forceinline__ void load_frags(uint32_t sA, uint32_t sB, int kp,
                                           int warp_m, int warp_n, int lrow, int lhalf,
                                           uint32_t a[2][4], uint32_t b[8][2]) {
    #pragma unroll
    for (int mt = 0; mt < 2; mt++)
        ldsm_x4(a[mt], sA + (warp_m * 32 + mt * 16 + lrow) * ROW_PAD + kp * 32 + lhalf);
    #pragma unroll
    for (int np = 0; np < 4; np++) {
        uint32_t r[4];
        ldsm_x4(r, sB + (warp_n * 64 + np * 16 + lrow) * ROW_PAD + kp * 32 + lhalf);
        b[2 * np + 0][0] = r[0]; b[2 * np + 0][1] = r[2];
        b[2 * np + 1][0] = r[1]; b[2 * np + 1][1] = r[3];
    }
}

extern "C" __global__ void __launch_bounds__(256, 2)
gemm_kernel(const float* __restrict__ bias, float* __restrict__ out) {
    extern __shared__ char smem[];
    const uint32_t sb = smem_u32(smem);
    const int tid = threadIdx.x;
    const int wid = tid >> 5;
    const int lane = tid & 31;
    const int warp_m = wid & 3;          // 4 warps along M (32 rows each)
    const int warp_n = wid >> 2;         // 2 warps along N (64 cols each)
    const int m0 = blockIdx.y * 128;
    const int n0 = blockIdx.x * 128;

    float c[2][8][4];
    #pragma unroll
    for (int mt = 0; mt < 2; mt++)
        #pragma unroll
        for (int nt = 0; nt < 8; nt++)
            #pragma unroll
            for (int j = 0; j < 4; j++) c[mt][nt][j] = 0.0f;

    // Prologue: fill stages 0..1
    #pragma unroll
    for (int s = 0; s < NSTAGE - 1; s++) {
        stage_copy(sb + s * STAGE_BYTES, s, m0, n0, tid);
        CP_COMMIT();
    }

    // ldmatrix lane addressing: row = lane&15, +16B for lanes 16..31
    const int lrow = lane & 15;
    const int lhalf = (lane >> 4) * 16;

    // Double-buffered fragment registers
    uint32_t afr[2][2][4], bfr[2][8][2];

    for (int kt = 0; kt < NKT; kt++) {
        CP_WAIT1();            // stage kt resident
        __syncthreads();       // visibility + write-safety for the copy below

        // Copy stage kt+2 into buffer (kt+2)%3 == (kt-1)%3 (compute done at kt-1).
        if (kt + NSTAGE - 1 < NKT)
            stage_copy(sb + ((kt + NSTAGE - 1) % NSTAGE) * STAGE_BYTES,
                       kt + NSTAGE - 1, m0, n0, tid);
        CP_COMMIT();

        const uint32_t sA = sb + (kt % NSTAGE) * STAGE_BYTES;
        const uint32_t sB = sA + A_STAGE;

        // Software-pipelined kpi loop: load kpi+1 while computing kpi.
        load_frags(sA, sB, 0, warp_m, warp_n, lrow, lhalf, afr[0], bfr[0]);
        #pragma unroll
        for (int kpi = 0; kpi < 4; kpi++) {
            const int cur = kpi & 1, nxt = cur ^ 1;
            if (kpi < 3)
                load_frags(sA, sB, kpi + 1, warp_m, warp_n, lrow, lhalf, afr[nxt], bfr[nxt]);
            #pragma unroll
            for (int mt = 0; mt < 2; mt++)
                #pragma unroll
                for (int nt = 0; nt < 8; nt++)
                    hmma16816(c[mt][nt], afr[cur][mt], bfr[cur][nt]);
        }
    }
    CP_WAIT0();

    // Epilogue: dequant + bias
    const float sx = __uint_as_float(g_amax_x) / 127.0f;
    const float sw = __uint_as_float(g_amax_w) / 127.0f;
    const float s = sx * sw;

    #pragma unroll
    for (int mt = 0; mt < 2; mt++) {
        #pragma unroll
        for (int half = 0; half < 2; half++) {
            int row = m0 + warp_m * 32 + mt * 16 + (lane >> 2) + half * 8;
            float* orow = out + (size_t)row * NN;
            #pragma unroll
            for (int nt = 0; nt < 8; nt++) {
                int col = n0 + warp_n * 64 + nt * 8 + (lane & 3) * 2;
                float2 o;
                o.x = c[mt][nt][half * 2 + 0] * s + __ldg(&bias[col]);
                o.y = c[mt][nt][half * 2 + 1] * s + __ldg(&bias[col + 1]);
                *reinterpret_cast<float2*>(orow + col) = o;
            }
        }
    }
}

// ============================================================================
// kernel_launch — graph-capturable, allocation-free
// ============================================================================
extern "C" void kernel_launch(void* const* d_in, const int* in_sizes, int n_in,
                              void* d_out, int out_size) {
    const float* x    = (const float*)d_in[0];   // [M, K]
    const float* w    = (const float*)d_in[1];   // [N, K]
    const float* bias = (const float*)d_in[2];   // [N]
    float* out        = (float*)d_out;           // [M, N]

    reset_kernel<<<1, 1>>>();
    absmax_both_kernel<<<3072, 256>>>(x, w);
    quant_both_kernel<<<12288, 256>>>(x, w);

    static bool attr_set = false;
    if (!attr_set) {
        cudaFuncSetAttribute(gemm_kernel, cudaFuncAttributeMaxDynamicSharedMemorySize, SMEM_BYTES);
        attr_set = true;
    }
    gemm_kernel<<<dim3(NN / 128, MM / 128, 1), 256, SMEM_BYTES>>>(bias, out);
}

// round 15
// speedup vs baseline: 1.1095x; 1.0093x over previous
#include <cuda_runtime.h>
#include <cuda_bf16.h>
#include <cstdint>
#include <cstddef>

// ============================================================================
// Problem dims
// ============================================================================
#define MM 8192
#define KK 4096
#define NN 4096

// ============================================================================
// Device scratch (allowed: __device__ globals, no runtime allocation)
// ============================================================================
__device__ unsigned g_amax_x;
__device__ unsigned g_amax_w;
__device__ __nv_bfloat16 g_xq[(size_t)MM * KK];   // quantized activations (exact ints in bf16)
__device__ __nv_bfloat16 g_wq[(size_t)NN * KK];   // quantized weights

// ============================================================================
// PTX helpers — family-generic (sm_80+ PTX only; NO tcgen05 on this target!)
// ============================================================================
__device__ __forceinline__ uint32_t smem_u32(const void* p) {
    uint32_t a;
    asm("{ .reg .u64 t; cvta.to.shared.u64 t, %1; cvt.u32.u64 %0, t; }" : "=r"(a) : "l"(p));
    return a;
}

#define CP_ASYNC16(dst, src) \
    asm volatile("cp.async.cg.shared.global [%0], [%1], 16;" :: "r"(dst), "l"(src) : "memory")
#define CP_COMMIT() asm volatile("cp.async.commit_group;" ::: "memory")
#define CP_WAIT1()  asm volatile("cp.async.wait_group 1;" ::: "memory")
#define CP_WAIT0()  asm volatile("cp.async.wait_group 0;" ::: "memory")

// bf16 warp MMA: D(16x8,f32) = A(16x16,bf16,row) * B(16x8,bf16,col) + D
__device__ __forceinline__ void hmma16816(float* c, const uint32_t* a, const uint32_t* b) {
    asm volatile(
        "mma.sync.aligned.m16n8k16.row.col.f32.bf16.bf16.f32 "
        "{%0,%1,%2,%3}, {%4,%5,%6,%7}, {%8,%9}, {%0,%1,%2,%3};"
        : "+f"(c[0]), "+f"(c[1]), "+f"(c[2]), "+f"(c[3])
        : "r"(a[0]), "r"(a[1]), "r"(a[2]), "r"(a[3]), "r"(b[0]), "r"(b[1]));
}

// ldmatrix x4: four 8x8 b16 matrices; lane l supplies the row address for its group
__device__ __forceinline__ void ldsm_x4(uint32_t* r, uint32_t addr) {
    asm volatile("ldmatrix.sync.aligned.m8n8.x4.shared.b16 {%0,%1,%2,%3}, [%4];"
                 : "=r"(r[0]), "=r"(r[1]), "=r"(r[2]), "=r"(r[3]) : "r"(addr));
}

// ============================================================================
// Pass 0: reset scales
// ============================================================================
__global__ void reset_kernel() {
    g_amax_x = 0u;
    g_amax_w = 0u;
}

// ============================================================================
// Pass 1: fused abs-max, MLP-4 restructure.
//   x: 8M float4, blocks [0,2048): exactly 16 float4/thread.
//   w: 4M float4, blocks [2048,3072): exactly 16 float4/thread.
//   4 groups of 4 independent loads into 4 independent accumulators
//   (breaks the serial fmax chain that held round-14 at ~4.5 TB/s).
// ============================================================================
__global__ void absmax_both_kernel(const float* __restrict__ x, const float* __restrict__ w) {
    const bool is_w = blockIdx.x >= 2048;
    const float4* __restrict__ in4 =
        reinterpret_cast<const float4*>(is_w ? w : x);
    const long bid = is_w ? (blockIdx.x - 2048) : blockIdx.x;
    const long S = (is_w ? 1024L : 2048L) * 256L;   // stride in float4
    long i = bid * 256 + threadIdx.x;

    float m0 = 0.0f, m1 = 0.0f, m2 = 0.0f, m3 = 0.0f;
    #pragma unroll
    for (int j = 0; j < 4; j++) {
        float4 v0 = in4[i];
        float4 v1 = in4[i + S];
        float4 v2 = in4[i + 2 * S];
        float4 v3 = in4[i + 3 * S];
        m0 = fmaxf(m0, fmaxf(fmaxf(fabsf(v0.x), fabsf(v0.y)), fmaxf(fabsf(v0.z), fabsf(v0.w))));
        m1 = fmaxf(m1, fmaxf(fmaxf(fabsf(v1.x), fabsf(v1.y)), fmaxf(fabsf(v1.z), fabsf(v1.w))));
        m2 = fmaxf(m2, fmaxf(fmaxf(fabsf(v2.x), fabsf(v2.y)), fmaxf(fabsf(v2.z), fabsf(v2.w))));
        m3 = fmaxf(m3, fmaxf(fmaxf(fabsf(v3.x), fabsf(v3.y)), fmaxf(fabsf(v3.z), fabsf(v3.w))));
        i += 4 * S;
    }
    float m = fmaxf(fmaxf(m0, m1), fmaxf(m2, m3));
    #pragma unroll
    for (int o = 16; o > 0; o >>= 1)
        m = fmaxf(m, __shfl_xor_sync(0xFFFFFFFFu, m, o));
    if ((threadIdx.x & 31) == 0)
        atomicMax(is_w ? &g_amax_w : &g_amax_x, __float_as_uint(m));
}

// ============================================================================
// Pass 2: fused quantize — clip(rint(t/scale), ±127), exact ints in bf16.
//   x: blocks [0,8192): exactly 4 float4/thread. w: [8192,12288): same.
//   All 4 loads issued before any compute/store (MLP-4).
// ============================================================================
__global__ void quant_both_kernel(const float* __restrict__ x, const float* __restrict__ w) {
    const bool is_w = blockIdx.x >= 8192;
    const float4* __restrict__ in4 =
        reinterpret_cast<const float4*>(is_w ? w : x);
    __nv_bfloat162* __restrict__ q2 =
        reinterpret_cast<__nv_bfloat162*>(is_w ? g_wq : g_xq);
    const long bid = is_w ? (blockIdx.x - 8192) : blockIdx.x;
    const long S = (is_w ? 4096L : 8192L) * 256L;   // stride in float4
    const long i0 = bid * 256 + threadIdx.x;
    const float scale = __uint_as_float(is_w ? g_amax_w : g_amax_x) / 127.0f;

    float4 v[4];
    #pragma unroll
    for (int j = 0; j < 4; j++) v[j] = in4[i0 + j * S];

    #pragma unroll
    for (int j = 0; j < 4; j++) {
        float a = fminf(fmaxf(rintf(v[j].x / scale), -127.0f), 127.0f);
        float b = fminf(fmaxf(rintf(v[j].y / scale), -127.0f), 127.0f);
        float c = fminf(fmaxf(rintf(v[j].z / scale), -127.0f), 127.0f);
        float d = fminf(fmaxf(rintf(v[j].w / scale), -127.0f), 127.0f);
        long i = i0 + j * S;
        q2[2 * i + 0] = __floats2bfloat162_rn(a, b);
        q2[2 * i + 1] = __floats2bfloat162_rn(c, d);
    }
}

// ============================================================================
// Pass 3: bf16 GEMM — UNCHANGED from round 14 (at the measured legacy-HMMA
// wall: ~14-15 cyc/HMMA/SMSP across every structural variant tried in
// rounds 5-14; tensor% pinned at ~53% == saturated half-width legacy path).
//   BM=128, BN=128, BK=64 (144B-padded rows); 8 warps 4(M)x2(N), 32x64 warp
//   tile; ldmatrix.x4; reg double-buffered fragments; 3-stage cp.async; occ 2.
// ============================================================================
static constexpr int BK = 64;
static constexpr int NKT = KK / BK;            // 64 k-tiles
static constexpr int ROW_PAD = 144;
static constexpr int A_STAGE = 128 * ROW_PAD;  // 18432 B
static constexpr int STAGE_BYTES = 2 * A_STAGE;
static constexpr int NSTAGE = 3;
static constexpr int SMEM_BYTES = NSTAGE * STAGE_BYTES;  // 110592 B (2 CTAs/SM)

__device__ __forceinline__ void stage_copy(uint32_t sbase, int kt, int m0, int n0, int tid) {
    const size_t kofs = (size_t)kt * BK;
    #pragma unroll
    for (int i = 0; i < 4; i++) {
        int idx = tid + i * 256;
        int row = idx >> 3, ch = idx & 7;
        CP_ASYNC16(sbase + row * ROW_PAD + ch * 16,
                   (const void*)(g_xq + (size_t)(m0 + row) * KK + kofs + ch * 8));
    }
    #pragma unroll
    for (int i = 0; i < 4; i++) {
        int idx = tid + i * 256;
        int row = idx >> 3, ch = idx & 7;
        CP_ASYNC16(sbase + A_STAGE + row * ROW_PAD + ch * 16,
                   (const void*)(g_wq + (size_t)(n0 + row) * KK + kofs + ch * 8));
    }
}

__device__ __forceinline__ void load_frags(uint32_t sA, uint32_t sB, int kp,
                                           int warp_m, int warp_n, int lrow, int lhalf,
                                           uint32_t a[2][4], uint32_t b[8][2]) {
    #pragma unroll
    for (int mt = 0; mt < 2; mt++)
        ldsm_x4(a[mt], sA + (warp_m * 32 + mt * 16 + lrow) * ROW_PAD + kp * 32 + lhalf);
    #pragma unroll
    for (int np = 0; np < 4; np++) {
        uint32_t r[4];
        ldsm_x4(r, sB + (warp_n * 64 + np * 16 + lrow) * ROW_PAD + kp * 32 + lhalf);
        b[2 * np + 0][0] = r[0]; b[2 * np + 0][1] = r[2];
        b[2 * np + 1][0] = r[1]; b[2 * np + 1][1] = r[3];
    }
}

extern "C" __global__ void __launch_bounds__(256, 2)
gemm_kernel(const float* __restrict__ bias, float* __restrict__ out) {
    extern __shared__ char smem[];
    const uint32_t sb = smem_u32(smem);
    const int tid = threadIdx.x;
    const int wid = tid >> 5;
    const int lane = tid & 31;
    const int warp_m = wid & 3;
    const int warp_n = wid >> 2;
    const int m0 = blockIdx.y * 128;
    const int n0 = blockIdx.x * 128;

    float c[2][8][4];
    #pragma unroll
    for (int mt = 0; mt < 2; mt++)
        #pragma unroll
        for (int nt = 0; nt < 8; nt++)
            #pragma unroll
            for (int j = 0; j < 4; j++) c[mt][nt][j] = 0.0f;

    #pragma unroll
    for (int s = 0; s < NSTAGE - 1; s++) {
        stage_copy(sb + s * STAGE_BYTES, s, m0, n0, tid);
        CP_COMMIT();
    }

    const int lrow = lane & 15;
    const int lhalf = (lane >> 4) * 16;

    uint32_t afr[2][2][4], bfr[2][8][2];

    for (int kt = 0; kt < NKT; kt++) {
        CP_WAIT1();
        __syncthreads();

        if (kt + NSTAGE - 1 < NKT)
            stage_copy(sb + ((kt + NSTAGE - 1) % NSTAGE) * STAGE_BYTES,
                       kt + NSTAGE - 1, m0, n0, tid);
        CP_COMMIT();

        const uint32_t sA = sb + (kt % NSTAGE) * STAGE_BYTES;
        const uint32_t sB = sA + A_STAGE;

        load_frags(sA, sB, 0, warp_m, warp_n, lrow, lhalf, afr[0], bfr[0]);
        #pragma unroll
        for (int kpi = 0; kpi < 4; kpi++) {
            const int cur = kpi & 1, nxt = cur ^ 1;
            if (kpi < 3)
                load_frags(sA, sB, kpi + 1, warp_m, warp_n, lrow, lhalf, afr[nxt], bfr[nxt]);
            #pragma unroll
            for (int mt = 0; mt < 2; mt++)
                #pragma unroll
                for (int nt = 0; nt < 8; nt++)
                    hmma16816(c[mt][nt], afr[cur][mt], bfr[cur][nt]);
        }
    }
    CP_WAIT0();

    // Epilogue: dequant + bias
    const float sx = __uint_as_float(g_amax_x) / 127.0f;
    const float sw = __uint_as_float(g_amax_w) / 127.0f;
    const float s = sx * sw;

    #pragma unroll
    for (int mt = 0; mt < 2; mt++) {
        #pragma unroll
        for (int half = 0; half < 2; half++) {
            int row = m0 + warp_m * 32 + mt * 16 + (lane >> 2) + half * 8;
            float* orow = out + (size_t)row * NN;
            #pragma unroll
            for (int nt = 0; nt < 8; nt++) {
                int col = n0 + warp_n * 64 + nt * 8 + (lane & 3) * 2;
                float2 o;
                o.x = c[mt][nt][half * 2 + 0] * s + __ldg(&bias[col]);
                o.y = c[mt][nt][half * 2 + 1] * s + __ldg(&bias[col + 1]);
                *reinterpret_cast<float2*>(orow + col) = o;
            }
        }
    }
}

// ============================================================================
// kernel_launch — graph-capturable, allocation-free
// ============================================================================
extern "C" void kernel_launch(void* const* d_in, const int* in_sizes, int n_in,
                              void* d_out, int out_size) {
    const float* x    = (const float*)d_in[0];   // [M, K]
    const float* w    = (const float*)d_in[1];   // [N, K]
    const float* bias = (const float*)d_in[2];   // [N]
    float* out        = (float*)d_out;           // [M, N]

    reset_kernel<<<1, 1>>>();
    absmax_both_kernel<<<3072, 256>>>(x, w);
    quant_both_kernel<<<12288, 256>>>(x, w);

    static bool attr_set = false;
    if (!attr_set) {
        cudaFuncSetAttribute(gemm_kernel, cudaFuncAttributeMaxDynamicSharedMemorySize, SMEM_BYTES);
        attr_set = true;
    }
    gemm_kernel<<<dim3(NN / 128, MM / 128, 1), 256, SMEM_BYTES>>>(bias, out);
}

// round 17
// speedup vs baseline: 1.2254x; 1.1044x over previous
#include <cuda_runtime.h>
#include <cuda_bf16.h>
#include <cstdint>
#include <cstddef>

// ============================================================================
// Problem dims
// ============================================================================
#define MM 8192
#define KK 4096
#define NN 4096

// ============================================================================
// Device scratch (allowed: __device__ globals, no runtime allocation)
// ============================================================================
__device__ unsigned g_amax_x;
__device__ unsigned g_amax_w;
__device__ __nv_bfloat16 g_xq[(size_t)MM * KK];   // quantized activations (exact ints in bf16)
__device__ __nv_bfloat16 g_wq[(size_t)NN * KK];   // quantized weights

// ============================================================================
// PTX helpers — family-generic (sm_80+ PTX only; NO tcgen05 on this target!)
// ============================================================================
__device__ __forceinline__ uint32_t smem_u32(const void* p) {
    uint32_t a;
    asm("{ .reg .u64 t; cvta.to.shared.u64 t, %1; cvt.u32.u64 %0, t; }" : "=r"(a) : "l"(p));
    return a;
}

#define CP_ASYNC16(dst, src) \
    asm volatile("cp.async.cg.shared.global [%0], [%1], 16;" :: "r"(dst), "l"(src) : "memory")
#define CP_COMMIT() asm volatile("cp.async.commit_group;" ::: "memory")
#define CP_WAIT1()  asm volatile("cp.async.wait_group 1;" ::: "memory")
#define CP_WAIT0()  asm volatile("cp.async.wait_group 0;" ::: "memory")

// bf16 warp MMA: D(16x8,f32) = A(16x16,bf16,row) * B(16x8,bf16,col) + D
__device__ __forceinline__ void hmma16816(float* c, const uint32_t* a, const uint32_t* b) {
    asm volatile(
        "mma.sync.aligned.m16n8k16.row.col.f32.bf16.bf16.f32 "
        "{%0,%1,%2,%3}, {%4,%5,%6,%7}, {%8,%9}, {%0,%1,%2,%3};"
        : "+f"(c[0]), "+f"(c[1]), "+f"(c[2]), "+f"(c[3])
        : "r"(a[0]), "r"(a[1]), "r"(a[2]), "r"(a[3]), "r"(b[0]), "r"(b[1]));
}

// ldmatrix x4: four 8x8 b16 matrices; lane l supplies the row address for its group
__device__ __forceinline__ void ldsm_x4(uint32_t* r, uint32_t addr) {
    asm volatile("ldmatrix.sync.aligned.m8n8.x4.shared.b16 {%0,%1,%2,%3}, [%4];"
                 : "=r"(r[0]), "=r"(r[1]), "=r"(r[2]), "=r"(r[3]) : "r"(addr));
}

// ============================================================================
// Pass 0: reset scales
// ============================================================================
__global__ void reset_kernel() {
    g_amax_x = 0u;
    g_amax_w = 0u;
}

// ============================================================================
// Pass 1: fused abs-max, MLP-8.
//   x: 8M float4, blocks [0,2048): 16 float4/thread as 2 iters x 8 indep loads.
//   w: 4M float4, blocks [2048,3072): same shape.
// ============================================================================
__global__ void absmax_both_kernel(const float* __restrict__ x, const float* __restrict__ w) {
    const bool is_w = blockIdx.x >= 2048;
    const float4* __restrict__ in4 = reinterpret_cast<const float4*>(is_w ? w : x);
    const long bid = is_w ? (blockIdx.x - 2048) : blockIdx.x;
    const long S = (is_w ? 1024L : 2048L) * 256L;   // stride in float4
    long i = bid * 256 + threadIdx.x;

    float m[8];
    #pragma unroll
    for (int j = 0; j < 8; j++) m[j] = 0.0f;

    #pragma unroll
    for (int it = 0; it < 2; it++) {
        float4 v[8];
        #pragma unroll
        for (int j = 0; j < 8; j++) v[j] = in4[i + j * S];
        #pragma unroll
        for (int j = 0; j < 8; j++)
            m[j] = fmaxf(m[j], fmaxf(fmaxf(fabsf(v[j].x), fabsf(v[j].y)),
                                     fmaxf(fabsf(v[j].z), fabsf(v[j].w))));
        i += 8 * S;
    }
    float mm = 0.0f;
    #pragma unroll
    for (int j = 0; j < 8; j++) mm = fmaxf(mm, m[j]);
    #pragma unroll
    for (int o = 16; o > 0; o >>= 1)
        mm = fmaxf(mm, __shfl_xor_sync(0xFFFFFFFFu, mm, o));
    if ((threadIdx.x & 31) == 0)
        atomicMax(is_w ? &g_amax_w : &g_amax_x, __float_as_uint(mm));
}

// ============================================================================
// Pass 2: fused quantize — clip(rint(t/scale), ±127), exact ints in bf16.
//   x: blocks [0,4096): exactly 8 float4/thread. w: [4096,6144): same.
//   All 8 loads issued before any compute/store (MLP-8).
// ============================================================================
__global__ void quant_both_kernel(const float* __restrict__ x, const float* __restrict__ w) {
    const bool is_w = blockIdx.x >= 4096;
    const float4* __restrict__ in4 = reinterpret_cast<const float4*>(is_w ? w : x);
    __nv_bfloat162* __restrict__ q2 =
        reinterpret_cast<__nv_bfloat162*>(is_w ? g_wq : g_xq);
    const long bid = is_w ? (blockIdx.x - 4096) : blockIdx.x;
    const long S = (is_w ? 2048L : 4096L) * 256L;   // stride in float4
    const long i0 = bid * 256 + threadIdx.x;
    const float scale = __uint_as_float(is_w ? g_amax_w : g_amax_x) / 127.0f;

    float4 v[8];
    #pragma unroll
    for (int j = 0; j < 8; j++) v[j] = in4[i0 + j * S];

    #pragma unroll
    for (int j = 0; j < 8; j++) {
        float a = fminf(fmaxf(rintf(v[j].x / scale), -127.0f), 127.0f);
        float b = fminf(fmaxf(rintf(v[j].y / scale), -127.0f), 127.0f);
        float c = fminf(fmaxf(rintf(v[j].z / scale), -127.0f), 127.0f);
        float d = fminf(fmaxf(rintf(v[j].w / scale), -127.0f), 127.0f);
        long i = i0 + j * S;
        q2[2 * i + 0] = __floats2bfloat162_rn(a, b);
        q2[2 * i + 1] = __floats2bfloat162_rn(c, d);
    }
}

// ============================================================================
// Pass 3: bf16 GEMM — structure at the measured legacy-HMMA wall (rounds 5-15:
// ~14-15 cyc/HMMA/SMSP effective across every warp/ILP/barrier variant).
//   BM=128, BN=128, BK=64 (144B-padded rows); 8 warps 4(M)x2(N), 32x64 warp
//   tile; ldmatrix.x4; reg double-buffered fragments; 3-stage cp.async; occ 2.
//   Round-16 tweaks: (a) first fragment loads issued BEFORE the stage_copy
//   instruction burst each tile (shorter critical path to first HMMA);
//   (b) bias hoisted to registers in the epilogue.
// ============================================================================
static constexpr int BK = 64;
static constexpr int NKT = KK / BK;            // 64 k-tiles
static constexpr int ROW_PAD = 144;
static constexpr int A_STAGE = 128 * ROW_PAD;  // 18432 B
static constexpr int STAGE_BYTES = 2 * A_STAGE;
static constexpr int NSTAGE = 3;
static constexpr int SMEM_BYTES = NSTAGE * STAGE_BYTES;  // 110592 B (2 CTAs/SM)

__device__ __forceinline__ void stage_copy(uint32_t sbase, int kt, int m0, int n0, int tid) {
    const size_t kofs = (size_t)kt * BK;
    #pragma unroll
    for (int i = 0; i < 4; i++) {
        int idx = tid + i * 256;
        int row = idx >> 3, ch = idx & 7;
        CP_ASYNC16(sbase + row * ROW_PAD + ch * 16,
                   (const void*)(g_xq + (size_t)(m0 + row) * KK + kofs + ch * 8));
    }
    #pragma unroll
    for (int i = 0; i < 4; i++) {
        int idx = tid + i * 256;
        int row = idx >> 3, ch = idx & 7;
        CP_ASYNC16(sbase + A_STAGE + row * ROW_PAD + ch * 16,
                   (const void*)(g_wq + (size_t)(n0 + row) * KK + kofs + ch * 8));
    }
}

__device__ __forceinline__ void load_frags(uint32_t sA, uint32_t sB, int kp,
                                           int warp_m, int warp_n, int lrow, int lhalf,
                                           uint32_t a[2][4], uint32_t b[8][2]) {
    #pragma unroll
    for (int mt = 0; mt < 2; mt++)
        ldsm_x4(a[mt], sA + (warp_m * 32 + mt * 16 + lrow) * ROW_PAD + kp * 32 + lhalf);
    #pragma unroll
    for (int np = 0; np < 4; np++) {
        uint32_t r[4];
        ldsm_x4(r, sB + (warp_n * 64 + np * 16 + lrow) * ROW_PAD + kp * 32 + lhalf);
        b[2 * np + 0][0] = r[0]; b[2 * np + 0][1] = r[2];
        b[2 * np + 1][0] = r[1]; b[2 * np + 1][1] = r[3];
    }
}

extern "C" __global__ void __launch_bounds__(256, 2)
gemm_kernel(const float* __restrict__ bias, float* __restrict__ out) {
    extern __shared__ char smem[];
    const uint32_t sb = smem_u32(smem);
    const int tid = threadIdx.x;
    const int wid = tid >> 5;
    const int lane = tid & 31;
    const int warp_m = wid & 3;
    const int warp_n = wid >> 2;
    const int m0 = blockIdx.y * 128;
    const int n0 = blockIdx.x * 128;

    float c[2][8][4];
    #pragma unroll
    for (int mt = 0; mt < 2; mt++)
        #pragma unroll
        for (int nt = 0; nt < 8; nt++)
            #pragma unroll
            for (int j = 0; j < 4; j++) c[mt][nt][j] = 0.0f;

    #pragma unroll
    for (int s = 0; s < NSTAGE - 1; s++) {
        stage_copy(sb + s * STAGE_BYTES, s, m0, n0, tid);
        CP_COMMIT();
    }

    const int lrow = lane & 15;
    const int lhalf = (lane >> 4) * 16;

    uint32_t afr[2][2][4], bfr[2][8][2];

    for (int kt = 0; kt < NKT; kt++) {
        CP_WAIT1();
        __syncthreads();

        const uint32_t sA = sb + (kt % NSTAGE) * STAGE_BYTES;
        const uint32_t sB = sA + A_STAGE;

        // Critical path first: kpi0 fragment loads for THIS tile...
        load_frags(sA, sB, 0, warp_m, warp_n, lrow, lhalf, afr[0], bfr[0]);

        // ...then the long cp.async burst for tile kt+2 (different buffer;
        // safety unchanged: its compute finished before the barrier above).
        if (kt + NSTAGE - 1 < NKT)
            stage_copy(sb + ((kt + NSTAGE - 1) % NSTAGE) * STAGE_BYTES,
                       kt + NSTAGE - 1, m0, n0, tid);
        CP_COMMIT();

        #pragma unroll
        for (int kpi = 0; kpi < 4; kpi++) {
            const int cur = kpi & 1, nxt = cur ^ 1;
            if (kpi < 3)
                load_frags(sA, sB, kpi + 1, warp_m, warp_n, lrow, lhalf, afr[nxt], bfr[nxt]);
            #pragma unroll
            for (int mt = 0; mt < 2; mt++)
                #pragma unroll
                for (int nt = 0; nt < 8; nt++)
                    hmma16816(c[mt][nt], afr[cur][mt], bfr[cur][nt]);
        }
    }
    CP_WAIT0();

    // Epilogue: dequant + bias (bias hoisted: loop-invariant across mt/half)
    const float sx = __uint_as_float(g_amax_x) / 127.0f;
    const float sw = __uint_as_float(g_amax_w) / 127.0f;
    const float s = sx * sw;

    float bias_r[16];
    #pragma unroll
    for (int nt = 0; nt < 8; nt++) {
        int col = n0 + warp_n * 64 + nt * 8 + (lane & 3) * 2;
        bias_r[2 * nt + 0] = __ldg(&bias[col]);
        bias_r[2 * nt + 1] = __ldg(&bias[col + 1]);
    }

    #pragma unroll
    for (int mt = 0; mt < 2; mt++) {
        #pragma unroll
        for (int half = 0; half < 2; half++) {
            int row = m0 + warp_m * 32 + mt * 16 + (lane >> 2) + half * 8;
            float* orow = out + (size_t)row * NN;
            #pragma unroll
            for (int nt = 0; nt < 8; nt++) {
                int col = n0 + warp_n * 64 + nt * 8 + (lane & 3) * 2;
                float2 o;
                o.x = c[mt][nt][half * 2 + 0] * s + bias_r[2 * nt + 0];
                o.y = c[mt][nt][half * 2 + 1] * s + bias_r[2 * nt + 1];
                *reinterpret_cast<float2*>(orow + col) = o;
            }
        }
    }
}

// ============================================================================
// kernel_launch — graph-capturable, allocation-free
// ============================================================================
extern "C" void kernel_launch(void* const* d_in, const int* in_sizes, int n_in,
                              void* d_out, int out_size) {
    const float* x    = (const float*)d_in[0];   // [M, K]
    const float* w    = (const float*)d_in[1];   // [N, K]
    const float* bias = (const float*)d_in[2];   // [N]
    float* out        = (float*)d_out;           // [M, N]

    reset_kernel<<<1, 1>>>();
    absmax_both_kernel<<<3072, 256>>>(x, w);
    quant_both_kernel<<<6144, 256>>>(x, w);

    static bool attr_set = false;
    if (!attr_set) {
        cudaFuncSetAttribute(gemm_kernel, cudaFuncAttributeMaxDynamicSharedMemorySize, SMEM_BYTES);
        attr_set = true;
    }
    gemm_kernel<<<dim3(NN / 128, MM / 128, 1), 256, SMEM_BYTES>>>(bias, out);
}